// round 12
// baseline (speedup 1.0000x reference)
#include <cuda_runtime.h>
#include <cuda_fp16.h>
#include <cstdint>
#include <cstddef>

// KMeansLayer via mma.sync m16n8k16 (fp16 2-way split, 3 passes) + fused softmax.
// out[n,k] = softmax_k( 20*(x_n . c_k) - 10*||c_k||^2 )   (||x||^2 cancels)
// x: [32768, 256] f32, centroids: [512, 256] f32, out: [32768, 512] f32.
// R12: smem-free mainloop. B fragments read straight from L2 (g_Bfrag is
//      0.5MB, fully L2-resident, identical for all CTAs); A read via L1
//      (shared across the CTA's warps). No barriers in the loop -> warps
//      decouple for free. MT=32, 256 thr, 2 CTAs/SM.

#define NRTOT   32768
#define KCLUST  512
#define DDIM    256
#define MT      32          // rows per CTA
#define NK      16          // k16 steps (DDIM/16)
#define NTHR    256
#define LOG2E   1.4426950408889634f

// device scratch
__device__ float g_csq10[KCLUST];
__device__ uint2 g_Bfrag[NK * 2 * 64 * 32];              // 0.5 MB fp16 B frags

// ---------------------------------------------------------------- helpers
__device__ __forceinline__ uint32_t packh2(float a, float b) {
    __half2 h = __floats2half2_rn(a, b);
    return *reinterpret_cast<uint32_t*>(&h);
}
__device__ __forceinline__ void mma16(float* d, const uint4& a, const uint2& b) {
    asm("mma.sync.aligned.m16n8k16.row.col.f32.f16.f16.f32 "
        "{%0,%1,%2,%3}, {%4,%5,%6,%7}, {%8,%9}, {%0,%1,%2,%3};"
        : "+f"(d[0]), "+f"(d[1]), "+f"(d[2]), "+f"(d[3])
        : "r"(a.x), "r"(a.y), "r"(a.z), "r"(a.w), "r"(b.x), "r"(b.y));
}

// ------------------------------------------------------ prologue: centroids
// One block per cluster n: 10*||c_n||^2 + fp16 hi/lo B fragments.
__global__ void prep_kernel(const float* __restrict__ cent) {
    __shared__ float cs[DDIM];
    __shared__ float part[64];
    const int n = blockIdx.x, t = threadIdx.x;

    if (t < 64) {
        float4 v = reinterpret_cast<const float4*>(cent)[n * (DDIM / 4) + t];
        reinterpret_cast<float4*>(cs)[t] = v;
        part[t] = v.x * v.x + v.y * v.y + v.z * v.z + v.w * v.w;
    }
    __syncthreads();
    if (t < 32) {
        float s = part[t] + part[t + 32];
#pragma unroll
        for (int o = 16; o > 0; o >>= 1) s += __shfl_xor_sync(0xffffffffu, s, o);
        if (t == 0) g_csq10[n] = 10.0f * s;
    }

    const int kc = t >> 3, hl = (t >> 2) & 1, tig = t & 3;
    const int k0 = kc * 16 + 2 * tig;
    const float v[4] = {cs[k0], cs[k0 + 1], cs[k0 + 8], cs[k0 + 9]};
    uint32_t p0, p1;
    if (hl == 0) {
        p0 = packh2(v[0], v[1]);
        p1 = packh2(v[2], v[3]);
    } else {
        float r[4];
#pragma unroll
        for (int i = 0; i < 4; ++i) {
            __half h = __float2half_rn(v[i]);
            r[i] = v[i] - __half2float(h);
        }
        p0 = packh2(r[0], r[1]);
        p1 = packh2(r[2], r[3]);
    }
    const int nt = n >> 3;
    const int lane = (n & 7) * 4 + tig;
    g_Bfrag[((kc * 2 + hl) * 64 + nt) * 32 + lane] = make_uint2(p0, p1);
}

// ------------------------------------------------------------ main kernel
__global__ __launch_bounds__(NTHR, 2)
void kmeans_mma(const float* __restrict__ x, float* __restrict__ out) {
    __shared__ float c10s[KCLUST];
    __shared__ float redM[MT * 8];
    __shared__ float redS[MT * 8];

    const int tid = threadIdx.x;
    const int nw = tid >> 5, lane = tid & 31;      // 8 warps, all cover rows 0..31
    const int grp = lane >> 2, tig = lane & 3;
    const int rowblk = blockIdx.x;

    for (int i = tid; i < KCLUST; i += NTHR) c10s[i] = g_csq10[i];
    __syncthreads();

    float acc[2][8][4];
#pragma unroll
    for (int mt = 0; mt < 2; ++mt)
#pragma unroll
        for (int nt = 0; nt < 8; ++nt)
#pragma unroll
            for (int r = 0; r < 4; ++r) acc[mt][nt][r] = 0.f;

    const float* xb = x + (size_t)(rowblk * MT) * DDIM;

    for (int k = 0; k < NK; ++k) {
        const int kc0 = k * 16 + 2 * tig;

        // ---- A: 4x LDG.64 per mt (L1-shared across the CTA's 8 warps),
        //      split into fp16 hi/lo fragments in registers ----
        uint4 ah[2], al[2];
#pragma unroll
        for (int mt = 0; mt < 2; ++mt) {
            const int R0 = mt * 16 + grp;
            float2 p[4];
            p[0] = *reinterpret_cast<const float2*>(&xb[(R0 + 0) * DDIM + kc0]);
            p[1] = *reinterpret_cast<const float2*>(&xb[(R0 + 8) * DDIM + kc0]);
            p[2] = *reinterpret_cast<const float2*>(&xb[(R0 + 0) * DDIM + kc0 + 8]);
            p[3] = *reinterpret_cast<const float2*>(&xb[(R0 + 8) * DDIM + kc0 + 8]);
            uint32_t hreg[4], lreg[4];
#pragma unroll
            for (int r = 0; r < 4; ++r) {
                __half hx = __float2half_rn(p[r].x);
                __half hy = __float2half_rn(p[r].y);
                const float rx = p[r].x - __half2float(hx);
                const float ry = p[r].y - __half2float(hy);
                __half2 hh = __halves2half2(hx, hy);
                hreg[r] = *reinterpret_cast<uint32_t*>(&hh);
                lreg[r] = packh2(rx, ry);
            }
            ah[mt] = make_uint4(hreg[0], hreg[1], hreg[2], hreg[3]);
            al[mt] = make_uint4(lreg[0], lreg[1], lreg[2], lreg[3]);
        }

        // ---- B: LDG.64 straight from L2-resident g_Bfrag; pass-major MMA ----
        const uint2* gBh = &g_Bfrag[((size_t)(k * 2 + 0) * 64) * 32 + lane];
        const uint2* gBl = &g_Bfrag[((size_t)(k * 2 + 1) * 64) * 32 + lane];
#pragma unroll
        for (int nc = 0; nc < 2; ++nc) {
            uint2 bh[4], bl[4];
#pragma unroll
            for (int j = 0; j < 4; ++j) {
                const int gnt = nw * 8 + nc * 4 + j;
                bh[j] = gBh[gnt * 32];
                bl[j] = gBl[gnt * 32];
            }
#pragma unroll
            for (int j = 0; j < 4; ++j) {           // hi*hi
                mma16(acc[0][nc * 4 + j], ah[0], bh[j]);
                mma16(acc[1][nc * 4 + j], ah[1], bh[j]);
            }
#pragma unroll
            for (int j = 0; j < 4; ++j) {           // hi*lo
                mma16(acc[0][nc * 4 + j], ah[0], bl[j]);
                mma16(acc[1][nc * 4 + j], ah[1], bl[j]);
            }
#pragma unroll
            for (int j = 0; j < 4; ++j) {           // lo*hi
                mma16(acc[0][nc * 4 + j], al[0], bh[j]);
                mma16(acc[1][nc * 4 + j], al[1], bh[j]);
            }
        }
    }

    // ---------------- fused softmax epilogue ----------------
#pragma unroll
    for (int mt = 0; mt < 2; ++mt)
#pragma unroll
        for (int nt = 0; nt < 8; ++nt)
#pragma unroll
            for (int r = 0; r < 4; ++r) {
                const int col = nw * 64 + nt * 8 + 2 * tig + (r & 1);
                acc[mt][nt][r] = 20.f * acc[mt][nt][r] - c10s[col];
            }

    float mloc[4];
#pragma unroll
    for (int rid = 0; rid < 4; ++rid) {
        const int mt = rid >> 1, rh = rid & 1;
        float m = -1e30f;
#pragma unroll
        for (int nt = 0; nt < 8; ++nt) {
            m = fmaxf(m, acc[mt][nt][rh * 2 + 0]);
            m = fmaxf(m, acc[mt][nt][rh * 2 + 1]);
        }
        m = fmaxf(m, __shfl_xor_sync(0xffffffffu, m, 1));
        m = fmaxf(m, __shfl_xor_sync(0xffffffffu, m, 2));
        float s = 0.f;
#pragma unroll
        for (int nt = 0; nt < 8; ++nt) {
#pragma unroll
            for (int c = 0; c < 2; ++c) {
                const float e = exp2f((acc[mt][nt][rh * 2 + c] - m) * LOG2E);
                acc[mt][nt][rh * 2 + c] = e;     // reuse regs as exp values
                s += e;
            }
        }
        s += __shfl_xor_sync(0xffffffffu, s, 1);
        s += __shfl_xor_sync(0xffffffffu, s, 2);
        mloc[rid] = m;
        if (tig == 0) {
            const int row = mt * 16 + rh * 8 + grp;
            redM[row * 8 + nw] = m;
            redS[row * 8 + nw] = s;
        }
    }
    __syncthreads();

#pragma unroll
    for (int rid = 0; rid < 4; ++rid) {
        const int mt = rid >> 1, rh = rid & 1;
        const int row = mt * 16 + rh * 8 + grp;
        float M = -1e30f;
        float mv[8];
#pragma unroll
        for (int j = 0; j < 8; ++j) {
            mv[j] = redM[row * 8 + j];
            M = fmaxf(M, mv[j]);
        }
        float S = 0.f;
#pragma unroll
        for (int j = 0; j < 8; ++j)
            S += redS[row * 8 + j] * exp2f((mv[j] - M) * LOG2E);
        const float scale = exp2f((mloc[rid] - M) * LOG2E) / S;

        float* orow = out + (size_t)(rowblk * MT + row) * KCLUST + nw * 64;
#pragma unroll
        for (int nt = 0; nt < 8; ++nt) {
            float2 v;
            v.x = acc[mt][nt][rh * 2 + 0] * scale;
            v.y = acc[mt][nt][rh * 2 + 1] * scale;
            *reinterpret_cast<float2*>(orow + nt * 8 + 2 * tig) = v;
        }
    }
}

// ---------------------------------------------------------------- launch
extern "C" void kernel_launch(void* const* d_in, const int* in_sizes, int n_in,
                              void* d_out, int out_size) {
    const float* x = (const float*)d_in[0];
    const float* cent = (const float*)d_in[1];
    if (n_in >= 2 && in_sizes[0] == KCLUST * DDIM && in_sizes[1] == NRTOT * DDIM) {
        const float* t = x; x = cent; cent = t;
    }
    float* out = (float*)d_out;

    prep_kernel<<<KCLUST, 128>>>(cent);
    kmeans_mma<<<NRTOT / MT, NTHR>>>(x, out);
}

// round 13
// speedup vs baseline: 1.3799x; 1.3799x over previous
#include <cuda_runtime.h>
#include <cuda_fp16.h>
#include <cstdint>
#include <cstddef>

// KMeansLayer via mma.sync m16n8k16 (fp16 2-way split, 3 passes) + fused softmax.
// out[n,k] = softmax_k( 20*(x_n . c_k) - 10*||c_k||^2 )   (||x||^2 cancels)
// x: [32768, 256] f32, centroids: [512, 256] f32, out: [32768, 512] f32.
// R13: R10 skeleton, but B fragments are read DIRECTLY from L2-resident
//      g_Bfrag via LDG.64 (fragment-packed -> 2 wavefronts/load, zero
//      redundancy); cp.async stage carries only A (2.5KB). This removes the
//      64KB/CTA-step B smem round-trip that capped R10's crossbar.

#define NRTOT   32768
#define KCLUST  512
#define DDIM    256
#define MT      32          // rows per CTA
#define NK      16          // k16 steps (DDIM/16)
#define NST     3           // pipeline stages
#define NTHR    256
#define LOG2E   1.4426950408889634f

#define A_ROW_F     20      // padded A row stride in floats (80B, 16B-aligned)
#define A_STG_BYTES (MT * A_ROW_F * 4)                   // 2560
#define STG_BYTES   A_STG_BYTES
#define SMEM_DYN    (NST * STG_BYTES)                    // 7680 dynamic (A stages)

// device scratch
__device__ float g_csq10[KCLUST];
__device__ uint2 g_Bfrag[NK * 2 * 64 * 32];              // 0.5 MB fp16 B frags

// ---------------------------------------------------------------- helpers
__device__ __forceinline__ uint32_t smem_u32(const void* p) {
    uint32_t a;
    asm("{ .reg .u64 t; cvta.to.shared.u64 t, %1; cvt.u32.u64 %0, t; }"
        : "=r"(a) : "l"(p));
    return a;
}
__device__ __forceinline__ uint32_t packh2(float a, float b) {
    __half2 h = __floats2half2_rn(a, b);
    return *reinterpret_cast<uint32_t*>(&h);
}
__device__ __forceinline__ void cp16(uint32_t dst, const void* src) {
    asm volatile("cp.async.cg.shared.global [%0], [%1], 16;"
                 :: "r"(dst), "l"(__cvta_generic_to_global(src)) : "memory");
}
#define CP_COMMIT() asm volatile("cp.async.commit_group;" ::: "memory")
#define CP_WAIT(n)  asm volatile("cp.async.wait_group %0;" :: "n"(n) : "memory")

__device__ __forceinline__ void mma16(float* d, const uint4& a, const uint2& b) {
    asm("mma.sync.aligned.m16n8k16.row.col.f32.f16.f16.f32 "
        "{%0,%1,%2,%3}, {%4,%5,%6,%7}, {%8,%9}, {%0,%1,%2,%3};"
        : "+f"(d[0]), "+f"(d[1]), "+f"(d[2]), "+f"(d[3])
        : "r"(a.x), "r"(a.y), "r"(a.z), "r"(a.w), "r"(b.x), "r"(b.y));
}

// ------------------------------------------------------ prologue: centroids
// One block per cluster n: 10*||c_n||^2 + fp16 hi/lo B fragments.
__global__ void prep_kernel(const float* __restrict__ cent) {
    __shared__ float cs[DDIM];
    __shared__ float part[64];
    const int n = blockIdx.x, t = threadIdx.x;

    if (t < 64) {
        float4 v = reinterpret_cast<const float4*>(cent)[n * (DDIM / 4) + t];
        reinterpret_cast<float4*>(cs)[t] = v;
        part[t] = v.x * v.x + v.y * v.y + v.z * v.z + v.w * v.w;
    }
    __syncthreads();
    if (t < 32) {
        float s = part[t] + part[t + 32];
#pragma unroll
        for (int o = 16; o > 0; o >>= 1) s += __shfl_xor_sync(0xffffffffu, s, o);
        if (t == 0) g_csq10[n] = 10.0f * s;
    }

    const int kc = t >> 3, hl = (t >> 2) & 1, tig = t & 3;
    const int k0 = kc * 16 + 2 * tig;
    const float v[4] = {cs[k0], cs[k0 + 1], cs[k0 + 8], cs[k0 + 9]};
    uint32_t p0, p1;
    if (hl == 0) {
        p0 = packh2(v[0], v[1]);
        p1 = packh2(v[2], v[3]);
    } else {
        float r[4];
#pragma unroll
        for (int i = 0; i < 4; ++i) {
            __half h = __float2half_rn(v[i]);
            r[i] = v[i] - __half2float(h);
        }
        p0 = packh2(r[0], r[1]);
        p1 = packh2(r[2], r[3]);
    }
    const int nt = n >> 3;
    const int lane = (n & 7) * 4 + tig;
    g_Bfrag[((kc * 2 + hl) * 64 + nt) * 32 + lane] = make_uint2(p0, p1);
}

// ------------------------------------------------------------ main kernel
// stage slot: A raw only (32 rows x 16 floats @ stride 20)
__device__ __forceinline__ void issue_stage(uint32_t sb, int s, int kc,
                                            const float* __restrict__ x,
                                            int rowblk, int tid) {
    if (tid < 128) {
        const uint32_t dst0 = sb + s * STG_BYTES;
        const int row = tid >> 2, part = tid & 3;
        const float* src = x + (size_t)(rowblk * MT + row) * DDIM + kc * 16 + part * 4;
        cp16(dst0 + row * (A_ROW_F * 4) + part * 16, src);
    }
}

__global__ __launch_bounds__(NTHR, 2)
void kmeans_mma(const float* __restrict__ x, float* __restrict__ out) {
    __shared__ float c10s[KCLUST];
    __shared__ float redM[MT * 8];
    __shared__ float redS[MT * 8];
    extern __shared__ char smem[];               // A stages
    const uint32_t sb = smem_u32(smem);

    const int tid = threadIdx.x;
    const int nw = tid >> 5, lane = tid & 31;    // 8 warps, all cover rows 0..31
    const int grp = lane >> 2, tig = lane & 3;
    const int rowblk = blockIdx.x;

    for (int i = tid; i < KCLUST; i += NTHR) c10s[i] = g_csq10[i];

    float acc[2][8][4];
#pragma unroll
    for (int mt = 0; mt < 2; ++mt)
#pragma unroll
        for (int nt = 0; nt < 8; ++nt)
#pragma unroll
            for (int r = 0; r < 4; ++r) acc[mt][nt][r] = 0.f;

    // pipeline prologue: fill 2 of 3 A stages
    issue_stage(sb, 0, 0, x, rowblk, tid);
    CP_COMMIT();
    issue_stage(sb, 1, 1, x, rowblk, tid);
    CP_COMMIT();
    CP_WAIT(1);
    __syncthreads();

    int sl = 0;
    for (int k = 0; k < NK; ++k) {
        if (k + 2 < NK) {
            int s2 = sl + 2;
            if (s2 >= NST) s2 -= NST;
            issue_stage(sb, s2, k + 2, x, rowblk, tid);
            CP_COMMIT();
        }

        const float* sAf = reinterpret_cast<const float*>(smem + sl * STG_BYTES);

        // ---- A: load raw f32 from smem, split into fp16 hi/lo fragments ----
        uint4 ah[2], al[2];
#pragma unroll
        for (int mt = 0; mt < 2; ++mt) {
            const int R0 = mt * 16 + grp;
            float2 p[4];
            p[0] = *reinterpret_cast<const float2*>(&sAf[(R0 + 0) * A_ROW_F + 2 * tig]);
            p[1] = *reinterpret_cast<const float2*>(&sAf[(R0 + 8) * A_ROW_F + 2 * tig]);
            p[2] = *reinterpret_cast<const float2*>(&sAf[(R0 + 0) * A_ROW_F + 2 * tig + 8]);
            p[3] = *reinterpret_cast<const float2*>(&sAf[(R0 + 8) * A_ROW_F + 2 * tig + 8]);
            uint32_t hreg[4], lreg[4];
#pragma unroll
            for (int r = 0; r < 4; ++r) {
                __half hx = __float2half_rn(p[r].x);
                __half hy = __float2half_rn(p[r].y);
                const float rx = p[r].x - __half2float(hx);
                const float ry = p[r].y - __half2float(hy);
                __half2 hh = __halves2half2(hx, hy);
                hreg[r] = *reinterpret_cast<uint32_t*>(&hh);
                lreg[r] = packh2(rx, ry);
            }
            ah[mt] = make_uint4(hreg[0], hreg[1], hreg[2], hreg[3]);
            al[mt] = make_uint4(lreg[0], lreg[1], lreg[2], lreg[3]);
        }

        // ---- B: direct LDG.64 from L2-resident frags; pass-major MMA ----
        const uint2* gBh = &g_Bfrag[((size_t)(k * 2 + 0) * 64) * 32 + lane];
        const uint2* gBl = &g_Bfrag[((size_t)(k * 2 + 1) * 64) * 32 + lane];
#pragma unroll
        for (int nc = 0; nc < 2; ++nc) {
            uint2 bh[4], bl[4];
#pragma unroll
            for (int j = 0; j < 4; ++j) {
                const int gnt = nw * 8 + nc * 4 + j;
                bh[j] = gBh[gnt * 32];
                bl[j] = gBl[gnt * 32];
            }
#pragma unroll
            for (int j = 0; j < 4; ++j) {           // hi*hi
                mma16(acc[0][nc * 4 + j], ah[0], bh[j]);
                mma16(acc[1][nc * 4 + j], ah[1], bh[j]);
            }
#pragma unroll
            for (int j = 0; j < 4; ++j) {           // hi*lo
                mma16(acc[0][nc * 4 + j], ah[0], bl[j]);
                mma16(acc[1][nc * 4 + j], ah[1], bl[j]);
            }
#pragma unroll
            for (int j = 0; j < 4; ++j) {           // lo*hi
                mma16(acc[0][nc * 4 + j], al[0], bh[j]);
                mma16(acc[1][nc * 4 + j], al[1], bh[j]);
            }
        }

        // end of step: stage k+1 must have landed before the next iteration.
        if (k < NK - 2) {
            CP_WAIT(1);
            __syncthreads();
        } else if (k == NK - 2) {
            CP_WAIT(0);
            __syncthreads();
        }
        if (++sl == NST) sl = 0;
    }

    // ---------------- fused softmax epilogue ----------------
#pragma unroll
    for (int mt = 0; mt < 2; ++mt)
#pragma unroll
        for (int nt = 0; nt < 8; ++nt)
#pragma unroll
            for (int r = 0; r < 4; ++r) {
                const int col = nw * 64 + nt * 8 + 2 * tig + (r & 1);
                acc[mt][nt][r] = 20.f * acc[mt][nt][r] - c10s[col];
            }

    float mloc[4];
#pragma unroll
    for (int rid = 0; rid < 4; ++rid) {
        const int mt = rid >> 1, rh = rid & 1;
        float m = -1e30f;
#pragma unroll
        for (int nt = 0; nt < 8; ++nt) {
            m = fmaxf(m, acc[mt][nt][rh * 2 + 0]);
            m = fmaxf(m, acc[mt][nt][rh * 2 + 1]);
        }
        m = fmaxf(m, __shfl_xor_sync(0xffffffffu, m, 1));
        m = fmaxf(m, __shfl_xor_sync(0xffffffffu, m, 2));
        float s = 0.f;
#pragma unroll
        for (int nt = 0; nt < 8; ++nt) {
#pragma unroll
            for (int c = 0; c < 2; ++c) {
                const float e = exp2f((acc[mt][nt][rh * 2 + c] - m) * LOG2E);
                acc[mt][nt][rh * 2 + c] = e;     // reuse regs as exp values
                s += e;
            }
        }
        s += __shfl_xor_sync(0xffffffffu, s, 1);
        s += __shfl_xor_sync(0xffffffffu, s, 2);
        mloc[rid] = m;
        if (tig == 0) {
            const int row = mt * 16 + rh * 8 + grp;
            redM[row * 8 + nw] = m;
            redS[row * 8 + nw] = s;
        }
    }
    __syncthreads();

#pragma unroll
    for (int rid = 0; rid < 4; ++rid) {
        const int mt = rid >> 1, rh = rid & 1;
        const int row = mt * 16 + rh * 8 + grp;
        float M = -1e30f;
        float mv[8];
#pragma unroll
        for (int j = 0; j < 8; ++j) {
            mv[j] = redM[row * 8 + j];
            M = fmaxf(M, mv[j]);
        }
        float S = 0.f;
#pragma unroll
        for (int j = 0; j < 8; ++j)
            S += redS[row * 8 + j] * exp2f((mv[j] - M) * LOG2E);
        const float scale = exp2f((mloc[rid] - M) * LOG2E) / S;

        float* orow = out + (size_t)(rowblk * MT + row) * KCLUST + nw * 64;
#pragma unroll
        for (int nt = 0; nt < 8; ++nt) {
            float2 v;
            v.x = acc[mt][nt][rh * 2 + 0] * scale;
            v.y = acc[mt][nt][rh * 2 + 1] * scale;
            *reinterpret_cast<float2*>(orow + nt * 8 + 2 * tig) = v;
        }
    }
}

// ---------------------------------------------------------------- launch
extern "C" void kernel_launch(void* const* d_in, const int* in_sizes, int n_in,
                              void* d_out, int out_size) {
    const float* x = (const float*)d_in[0];
    const float* cent = (const float*)d_in[1];
    if (n_in >= 2 && in_sizes[0] == KCLUST * DDIM && in_sizes[1] == NRTOT * DDIM) {
        const float* t = x; x = cent; cent = t;
    }
    float* out = (float*)d_out;

    prep_kernel<<<KCLUST, 128>>>(cent);
    kmeans_mma<<<NRTOT / MT, NTHR, SMEM_DYN>>>(x, out);
}

// round 14
// speedup vs baseline: 1.5584x; 1.1294x over previous
#include <cuda_runtime.h>
#include <cuda_fp16.h>
#include <cstdint>
#include <cstddef>

// KMeansLayer via mma.sync m16n8k16 (fp16 2-way split, 3 passes) + fused softmax.
// out[n,k] = softmax_k( 20*(x_n . c_k) - 10*||c_k||^2 )   (||x||^2 cancels)
// x: [32768, 256] f32, centroids: [512, 256] f32, out: [32768, 512] f32.
// R14: barrier-free mainloop. A tile converted ONCE per CTA into resident
//      smem fragments (kills 8x-redundant per-step cvt + all A sync);
//      B fragments register-double-buffered straight from L2/L1 with
//      chunk-level prefetch. No __syncthreads / cp.async in the loop ->
//      warps fully decoupled. MT=32, 256 thr, 2 CTAs/SM.

#define NRTOT   32768
#define KCLUST  512
#define DDIM    256
#define MT      32          // rows per CTA
#define NK      16          // k16 steps (DDIM/16)
#define NTHR    256
#define LOG2E   1.4426950408889634f

// device scratch
__device__ float g_csq10[KCLUST];
__device__ uint2 g_Bfrag[NK * 2 * 64 * 32];              // 0.5 MB fp16 B frags

// ---------------------------------------------------------------- helpers
__device__ __forceinline__ uint32_t packh2(float a, float b) {
    __half2 h = __floats2half2_rn(a, b);
    return *reinterpret_cast<uint32_t*>(&h);
}
__device__ __forceinline__ void mma16(float* d, const uint4& a, const uint2& b) {
    asm("mma.sync.aligned.m16n8k16.row.col.f32.f16.f16.f32 "
        "{%0,%1,%2,%3}, {%4,%5,%6,%7}, {%8,%9}, {%0,%1,%2,%3};"
        : "+f"(d[0]), "+f"(d[1]), "+f"(d[2]), "+f"(d[3])
        : "r"(a.x), "r"(a.y), "r"(a.z), "r"(a.w), "r"(b.x), "r"(b.y));
}

// ------------------------------------------------------ prologue: centroids
// One block per cluster n: 10*||c_n||^2 + fp16 hi/lo B fragments.
// Frag layout: g_Bfrag[((kc*2 + hl)*64 + nt)*32 + lane], uint2.
__global__ void prep_kernel(const float* __restrict__ cent) {
    __shared__ float cs[DDIM];
    __shared__ float part[64];
    const int n = blockIdx.x, t = threadIdx.x;

    if (t < 64) {
        float4 v = reinterpret_cast<const float4*>(cent)[n * (DDIM / 4) + t];
        reinterpret_cast<float4*>(cs)[t] = v;
        part[t] = v.x * v.x + v.y * v.y + v.z * v.z + v.w * v.w;
    }
    __syncthreads();
    if (t < 32) {
        float s = part[t] + part[t + 32];
#pragma unroll
        for (int o = 16; o > 0; o >>= 1) s += __shfl_xor_sync(0xffffffffu, s, o);
        if (t == 0) g_csq10[n] = 10.0f * s;
    }

    const int kc = t >> 3, hl = (t >> 2) & 1, tig = t & 3;
    const int k0 = kc * 16 + 2 * tig;
    const float v[4] = {cs[k0], cs[k0 + 1], cs[k0 + 8], cs[k0 + 9]};
    uint32_t p0, p1;
    if (hl == 0) {
        p0 = packh2(v[0], v[1]);
        p1 = packh2(v[2], v[3]);
    } else {
        float r[4];
#pragma unroll
        for (int i = 0; i < 4; ++i) {
            __half h = __float2half_rn(v[i]);
            r[i] = v[i] - __half2float(h);
        }
        p0 = packh2(r[0], r[1]);
        p1 = packh2(r[2], r[3]);
    }
    const int nt = n >> 3;
    const int lane = (n & 7) * 4 + tig;
    g_Bfrag[((kc * 2 + hl) * 64 + nt) * 32 + lane] = make_uint2(p0, p1);
}

// ------------------------------------------------------------ main kernel
// A-frag smem layout: afrag[(((kc*2 + hl)*2 + mt)*32 + lane)*4 + r] (uint32)
__global__ __launch_bounds__(NTHR, 2)
void kmeans_mma(const float* __restrict__ x, float* __restrict__ out) {
    __shared__ uint32_t afrag[NK * 2 * 2 * 32 * 4];      // 32 KB resident A frags
    __shared__ float c10s[KCLUST];
    __shared__ float redM[MT * 8];
    __shared__ float redS[MT * 8];

    const int tid = threadIdx.x;
    const int nw = tid >> 5, lane = tid & 31;      // 8 warps, all cover rows 0..31
    const int grp = lane >> 2, tig = lane & 3;
    const int rowblk = blockIdx.x;

    for (int i = tid; i < KCLUST; i += NTHR) c10s[i] = g_csq10[i];

    // ---- one-time A conversion: thread owns (row = tid>>3, k-chunk = tid&7) ----
    {
        const int row = tid >> 3, chunk = tid & 7;
        const int mt = row >> 4, rbit = (row >> 3) & 1, rgrp = row & 7;
        const float* src = x + (size_t)(rowblk * MT + row) * DDIM + chunk * 32;
        float f[32];
#pragma unroll
        for (int i = 0; i < 8; ++i) {
            float4 v = reinterpret_cast<const float4*>(src)[i];
            f[4 * i + 0] = v.x; f[4 * i + 1] = v.y;
            f[4 * i + 2] = v.z; f[4 * i + 3] = v.w;
        }
#pragma unroll
        for (int kc2 = 0; kc2 < 2; ++kc2) {
            const int kc = chunk * 2 + kc2;
#pragma unroll
            for (int koff = 0; koff < 2; ++koff) {
#pragma unroll
                for (int tg = 0; tg < 4; ++tg) {
                    const int li = kc2 * 16 + koff * 8 + tg * 2;
                    const float v0 = f[li], v1 = f[li + 1];
                    const __half h0 = __float2half_rn(v0);
                    const __half h1 = __float2half_rn(v1);
                    const __half2 hh = __halves2half2(h0, h1);
                    const uint32_t hi = *reinterpret_cast<const uint32_t*>(&hh);
                    const uint32_t lo = packh2(v0 - __half2float(h0),
                                               v1 - __half2float(h1));
                    const int ln = rgrp * 4 + tg;
                    const int r = rbit + 2 * koff;
                    afrag[(((kc * 2 + 0) * 2 + mt) * 32 + ln) * 4 + r] = hi;
                    afrag[(((kc * 2 + 1) * 2 + mt) * 32 + ln) * 4 + r] = lo;
                }
            }
        }
    }
    __syncthreads();   // afrag + c10s published; NO more syncs until epilogue

    float acc[2][8][4];
#pragma unroll
    for (int mt = 0; mt < 2; ++mt)
#pragma unroll
        for (int nt = 0; nt < 8; ++nt)
#pragma unroll
            for (int r = 0; r < 4; ++r) acc[mt][nt][r] = 0.f;

    // ---- mainloop: B register double-buffer (parity = nc, k-invariant) ----
    uint2 bh0[4], bl0[4], bh1[4], bl1[4];
#pragma unroll
    for (int j = 0; j < 4; ++j) {                 // preload chunk (k=0, nc=0)
        const int gnt = nw * 8 + j;
        bh0[j] = g_Bfrag[((0 * 2 + 0) * 64 + gnt) * 32 + lane];
        bl0[j] = g_Bfrag[((0 * 2 + 1) * 64 + gnt) * 32 + lane];
    }

    for (int k = 0; k < NK; ++k) {
        // A fragments for this k (resident smem, conflict-free LDS.128)
        uint4 ah[2], al[2];
#pragma unroll
        for (int mt = 0; mt < 2; ++mt) {
            ah[mt] = *reinterpret_cast<const uint4*>(
                &afrag[(((k * 2 + 0) * 2 + mt) * 32 + lane) * 4]);
            al[mt] = *reinterpret_cast<const uint4*>(
                &afrag[(((k * 2 + 1) * 2 + mt) * 32 + lane) * 4]);
        }

        // prefetch chunk (k, nc=1) into buf1
#pragma unroll
        for (int j = 0; j < 4; ++j) {
            const int gnt = nw * 8 + 4 + j;
            bh1[j] = g_Bfrag[((k * 2 + 0) * 64 + gnt) * 32 + lane];
            bl1[j] = g_Bfrag[((k * 2 + 1) * 64 + gnt) * 32 + lane];
        }

        // MMA chunk (k, nc=0) from buf0, pass-major
#pragma unroll
        for (int j = 0; j < 4; ++j) {
            mma16(acc[0][j], ah[0], bh0[j]);
            mma16(acc[1][j], ah[1], bh0[j]);
        }
#pragma unroll
        for (int j = 0; j < 4; ++j) {
            mma16(acc[0][j], ah[0], bl0[j]);
            mma16(acc[1][j], ah[1], bl0[j]);
        }
#pragma unroll
        for (int j = 0; j < 4; ++j) {
            mma16(acc[0][j], al[0], bh0[j]);
            mma16(acc[1][j], al[1], bh0[j]);
        }

        // prefetch chunk (k+1, nc=0) into buf0 (clamped; redundant on last k)
        const int kn = (k + 1 < NK) ? (k + 1) : 0;
#pragma unroll
        for (int j = 0; j < 4; ++j) {
            const int gnt = nw * 8 + j;
            bh0[j] = g_Bfrag[((kn * 2 + 0) * 64 + gnt) * 32 + lane];
            bl0[j] = g_Bfrag[((kn * 2 + 1) * 64 + gnt) * 32 + lane];
        }

        // MMA chunk (k, nc=1) from buf1, pass-major
#pragma unroll
        for (int j = 0; j < 4; ++j) {
            mma16(acc[0][4 + j], ah[0], bh1[j]);
            mma16(acc[1][4 + j], ah[1], bh1[j]);
        }
#pragma unroll
        for (int j = 0; j < 4; ++j) {
            mma16(acc[0][4 + j], ah[0], bl1[j]);
            mma16(acc[1][4 + j], ah[1], bl1[j]);
        }
#pragma unroll
        for (int j = 0; j < 4; ++j) {
            mma16(acc[0][4 + j], al[0], bh1[j]);
            mma16(acc[1][4 + j], al[1], bh1[j]);
        }
    }

    // ---------------- fused softmax epilogue ----------------
#pragma unroll
    for (int mt = 0; mt < 2; ++mt)
#pragma unroll
        for (int nt = 0; nt < 8; ++nt)
#pragma unroll
            for (int r = 0; r < 4; ++r) {
                const int col = nw * 64 + nt * 8 + 2 * tig + (r & 1);
                acc[mt][nt][r] = 20.f * acc[mt][nt][r] - c10s[col];
            }

    float mloc[4];
#pragma unroll
    for (int rid = 0; rid < 4; ++rid) {
        const int mt = rid >> 1, rh = rid & 1;
        float m = -1e30f;
#pragma unroll
        for (int nt = 0; nt < 8; ++nt) {
            m = fmaxf(m, acc[mt][nt][rh * 2 + 0]);
            m = fmaxf(m, acc[mt][nt][rh * 2 + 1]);
        }
        m = fmaxf(m, __shfl_xor_sync(0xffffffffu, m, 1));
        m = fmaxf(m, __shfl_xor_sync(0xffffffffu, m, 2));
        float s = 0.f;
#pragma unroll
        for (int nt = 0; nt < 8; ++nt) {
#pragma unroll
            for (int c = 0; c < 2; ++c) {
                const float e = exp2f((acc[mt][nt][rh * 2 + c] - m) * LOG2E);
                acc[mt][nt][rh * 2 + c] = e;     // reuse regs as exp values
                s += e;
            }
        }
        s += __shfl_xor_sync(0xffffffffu, s, 1);
        s += __shfl_xor_sync(0xffffffffu, s, 2);
        mloc[rid] = m;
        if (tig == 0) {
            const int row = mt * 16 + rh * 8 + grp;
            redM[row * 8 + nw] = m;
            redS[row * 8 + nw] = s;
        }
    }
    __syncthreads();

#pragma unroll
    for (int rid = 0; rid < 4; ++rid) {
        const int mt = rid >> 1, rh = rid & 1;
        const int row = mt * 16 + rh * 8 + grp;
        float M = -1e30f;
        float mv[8];
#pragma unroll
        for (int j = 0; j < 8; ++j) {
            mv[j] = redM[row * 8 + j];
            M = fmaxf(M, mv[j]);
        }
        float S = 0.f;
#pragma unroll
        for (int j = 0; j < 8; ++j)
            S += redS[row * 8 + j] * exp2f((mv[j] - M) * LOG2E);
        const float scale = exp2f((mloc[rid] - M) * LOG2E) / S;

        float* orow = out + (size_t)(rowblk * MT + row) * KCLUST + nw * 64;
#pragma unroll
        for (int nt = 0; nt < 8; ++nt) {
            float2 v;
            v.x = acc[mt][nt][rh * 2 + 0] * scale;
            v.y = acc[mt][nt][rh * 2 + 1] * scale;
            *reinterpret_cast<float2*>(orow + nt * 8 + 2 * tig) = v;
        }
    }
}

// ---------------------------------------------------------------- launch
extern "C" void kernel_launch(void* const* d_in, const int* in_sizes, int n_in,
                              void* d_out, int out_size) {
    const float* x = (const float*)d_in[0];
    const float* cent = (const float*)d_in[1];
    if (n_in >= 2 && in_sizes[0] == KCLUST * DDIM && in_sizes[1] == NRTOT * DDIM) {
        const float* t = x; x = cent; cent = t;
    }
    float* out = (float*)d_out;

    prep_kernel<<<KCLUST, 128>>>(cent);
    kmeans_mma<<<NRTOT / MT, NTHR>>>(x, out);
}

// round 15
// speedup vs baseline: 1.5744x; 1.0102x over previous
#include <cuda_runtime.h>
#include <cuda_fp16.h>
#include <cstdint>
#include <cstddef>

// KMeansLayer via mma.sync m16n8k16 (fp16 2-way split, 3 passes) + fused softmax.
// out[n,k] = softmax_k( 20*(x_n . c_k) - 10*||c_k||^2 )   (||x||^2 cancels)
// x: [32768, 256] f32, centroids: [512, 256] f32, out: [32768, 512] f32.
// R15: R14 + per-warp k-stagger (warp nw starts at k-chunk nw, wraps mod 16).
//      Breaks the all-warps-lockstep L1tex convoy that idled the tensor pipe:
//      load bursts now hit the memory queue at 8 phases, so some warp always
//      has HMMAs in flight. Barrier-free loop, resident-A frags, B reg-
//      double-buffered from L2/L1. MT=32, 256 thr, 2 CTAs/SM.

#define NRTOT   32768
#define KCLUST  512
#define DDIM    256
#define MT      32          // rows per CTA
#define NK      16          // k16 steps (DDIM/16)
#define NTHR    256
#define LOG2E   1.4426950408889634f

// device scratch
__device__ float g_csq10[KCLUST];
__device__ uint2 g_Bfrag[NK * 2 * 64 * 32];              // 0.5 MB fp16 B frags

// ---------------------------------------------------------------- helpers
__device__ __forceinline__ uint32_t packh2(float a, float b) {
    __half2 h = __floats2half2_rn(a, b);
    return *reinterpret_cast<uint32_t*>(&h);
}
__device__ __forceinline__ void mma16(float* d, const uint4& a, const uint2& b) {
    asm("mma.sync.aligned.m16n8k16.row.col.f32.f16.f16.f32 "
        "{%0,%1,%2,%3}, {%4,%5,%6,%7}, {%8,%9}, {%0,%1,%2,%3};"
        : "+f"(d[0]), "+f"(d[1]), "+f"(d[2]), "+f"(d[3])
        : "r"(a.x), "r"(a.y), "r"(a.z), "r"(a.w), "r"(b.x), "r"(b.y));
}

// ------------------------------------------------------ prologue: centroids
// One block per cluster n: 10*||c_n||^2 + fp16 hi/lo B fragments.
// Frag layout: g_Bfrag[((kc*2 + hl)*64 + nt)*32 + lane], uint2.
__global__ void prep_kernel(const float* __restrict__ cent) {
    __shared__ float cs[DDIM];
    __shared__ float part[64];
    const int n = blockIdx.x, t = threadIdx.x;

    if (t < 64) {
        float4 v = reinterpret_cast<const float4*>(cent)[n * (DDIM / 4) + t];
        reinterpret_cast<float4*>(cs)[t] = v;
        part[t] = v.x * v.x + v.y * v.y + v.z * v.z + v.w * v.w;
    }
    __syncthreads();
    if (t < 32) {
        float s = part[t] + part[t + 32];
#pragma unroll
        for (int o = 16; o > 0; o >>= 1) s += __shfl_xor_sync(0xffffffffu, s, o);
        if (t == 0) g_csq10[n] = 10.0f * s;
    }

    const int kc = t >> 3, hl = (t >> 2) & 1, tig = t & 3;
    const int k0 = kc * 16 + 2 * tig;
    const float v[4] = {cs[k0], cs[k0 + 1], cs[k0 + 8], cs[k0 + 9]};
    uint32_t p0, p1;
    if (hl == 0) {
        p0 = packh2(v[0], v[1]);
        p1 = packh2(v[2], v[3]);
    } else {
        float r[4];
#pragma unroll
        for (int i = 0; i < 4; ++i) {
            __half h = __float2half_rn(v[i]);
            r[i] = v[i] - __half2float(h);
        }
        p0 = packh2(r[0], r[1]);
        p1 = packh2(r[2], r[3]);
    }
    const int nt = n >> 3;
    const int lane = (n & 7) * 4 + tig;
    g_Bfrag[((kc * 2 + hl) * 64 + nt) * 32 + lane] = make_uint2(p0, p1);
}

// ------------------------------------------------------------ main kernel
// A-frag smem layout: afrag[(((kc*2 + hl)*2 + mt)*32 + lane)*4 + r] (uint32)
__global__ __launch_bounds__(NTHR, 2)
void kmeans_mma(const float* __restrict__ x, float* __restrict__ out) {
    __shared__ uint32_t afrag[NK * 2 * 2 * 32 * 4];      // 32 KB resident A frags
    __shared__ float c10s[KCLUST];
    __shared__ float redM[MT * 8];
    __shared__ float redS[MT * 8];

    const int tid = threadIdx.x;
    const int nw = tid >> 5, lane = tid & 31;      // 8 warps, all cover rows 0..31
    const int grp = lane >> 2, tig = lane & 3;
    const int rowblk = blockIdx.x;

    for (int i = tid; i < KCLUST; i += NTHR) c10s[i] = g_csq10[i];

    // ---- one-time A conversion: thread owns (row = tid>>3, k-chunk = tid&7) ----
    {
        const int row = tid >> 3, chunk = tid & 7;
        const int mt = row >> 4, rbit = (row >> 3) & 1, rgrp = row & 7;
        const float* src = x + (size_t)(rowblk * MT + row) * DDIM + chunk * 32;
        float f[32];
#pragma unroll
        for (int i = 0; i < 8; ++i) {
            float4 v = reinterpret_cast<const float4*>(src)[i];
            f[4 * i + 0] = v.x; f[4 * i + 1] = v.y;
            f[4 * i + 2] = v.z; f[4 * i + 3] = v.w;
        }
#pragma unroll
        for (int kc2 = 0; kc2 < 2; ++kc2) {
            const int kc = chunk * 2 + kc2;
#pragma unroll
            for (int koff = 0; koff < 2; ++koff) {
#pragma unroll
                for (int tg = 0; tg < 4; ++tg) {
                    const int li = kc2 * 16 + koff * 8 + tg * 2;
                    const float v0 = f[li], v1 = f[li + 1];
                    const __half h0 = __float2half_rn(v0);
                    const __half h1 = __float2half_rn(v1);
                    const __half2 hh = __halves2half2(h0, h1);
                    const uint32_t hi = *reinterpret_cast<const uint32_t*>(&hh);
                    const uint32_t lo = packh2(v0 - __half2float(h0),
                                               v1 - __half2float(h1));
                    const int ln = rgrp * 4 + tg;
                    const int r = rbit + 2 * koff;
                    afrag[(((kc * 2 + 0) * 2 + mt) * 32 + ln) * 4 + r] = hi;
                    afrag[(((kc * 2 + 1) * 2 + mt) * 32 + ln) * 4 + r] = lo;
                }
            }
        }
    }
    __syncthreads();   // afrag + c10s published; NO more syncs until epilogue

    float acc[2][8][4];
#pragma unroll
    for (int mt = 0; mt < 2; ++mt)
#pragma unroll
        for (int nt = 0; nt < 8; ++nt)
#pragma unroll
            for (int r = 0; r < 4; ++r) acc[mt][nt][r] = 0.f;

    // ---- mainloop: per-warp k-stagger + B register double-buffer ----
    int kk = nw;                                   // warp nw starts at chunk nw
    uint2 bh0[4], bl0[4], bh1[4], bl1[4];
#pragma unroll
    for (int j = 0; j < 4; ++j) {                  // preload chunk (kk, nc=0)
        const int gnt = nw * 8 + j;
        bh0[j] = g_Bfrag[((kk * 2 + 0) * 64 + gnt) * 32 + lane];
        bl0[j] = g_Bfrag[((kk * 2 + 1) * 64 + gnt) * 32 + lane];
    }

    for (int k = 0; k < NK; ++k) {
        // A fragments for chunk kk (resident smem, conflict-free LDS.128)
        uint4 ah[2], al[2];
#pragma unroll
        for (int mt = 0; mt < 2; ++mt) {
            ah[mt] = *reinterpret_cast<const uint4*>(
                &afrag[(((kk * 2 + 0) * 2 + mt) * 32 + lane) * 4]);
            al[mt] = *reinterpret_cast<const uint4*>(
                &afrag[(((kk * 2 + 1) * 2 + mt) * 32 + lane) * 4]);
        }

        // prefetch chunk (kk, nc=1) into buf1
#pragma unroll
        for (int j = 0; j < 4; ++j) {
            const int gnt = nw * 8 + 4 + j;
            bh1[j] = g_Bfrag[((kk * 2 + 0) * 64 + gnt) * 32 + lane];
            bl1[j] = g_Bfrag[((kk * 2 + 1) * 64 + gnt) * 32 + lane];
        }

        // MMA chunk (kk, nc=0) from buf0, pass-major
#pragma unroll
        for (int j = 0; j < 4; ++j) {
            mma16(acc[0][j], ah[0], bh0[j]);
            mma16(acc[1][j], ah[1], bh0[j]);
        }
#pragma unroll
        for (int j = 0; j < 4; ++j) {
            mma16(acc[0][j], ah[0], bl0[j]);
            mma16(acc[1][j], ah[1], bl0[j]);
        }
#pragma unroll
        for (int j = 0; j < 4; ++j) {
            mma16(acc[0][j], al[0], bh0[j]);
            mma16(acc[1][j], al[1], bh0[j]);
        }

        // prefetch chunk (kk+1 wrap, nc=0) into buf0 (redundant on last k)
        int kn = kk + 1;
        if (kn == NK) kn = 0;
#pragma unroll
        for (int j = 0; j < 4; ++j) {
            const int gnt = nw * 8 + j;
            bh0[j] = g_Bfrag[((kn * 2 + 0) * 64 + gnt) * 32 + lane];
            bl0[j] = g_Bfrag[((kn * 2 + 1) * 64 + gnt) * 32 + lane];
        }

        // MMA chunk (kk, nc=1) from buf1, pass-major
#pragma unroll
        for (int j = 0; j < 4; ++j) {
            mma16(acc[0][4 + j], ah[0], bh1[j]);
            mma16(acc[1][4 + j], ah[1], bh1[j]);
        }
#pragma unroll
        for (int j = 0; j < 4; ++j) {
            mma16(acc[0][4 + j], ah[0], bl1[j]);
            mma16(acc[1][4 + j], ah[1], bl1[j]);
        }
#pragma unroll
        for (int j = 0; j < 4; ++j) {
            mma16(acc[0][4 + j], al[0], bh1[j]);
            mma16(acc[1][4 + j], al[1], bh1[j]);
        }

        kk = kn;
    }

    // ---------------- fused softmax epilogue ----------------
#pragma unroll
    for (int mt = 0; mt < 2; ++mt)
#pragma unroll
        for (int nt = 0; nt < 8; ++nt)
#pragma unroll
            for (int r = 0; r < 4; ++r) {
                const int col = nw * 64 + nt * 8 + 2 * tig + (r & 1);
                acc[mt][nt][r] = 20.f * acc[mt][nt][r] - c10s[col];
            }

    float mloc[4];
#pragma unroll
    for (int rid = 0; rid < 4; ++rid) {
        const int mt = rid >> 1, rh = rid & 1;
        float m = -1e30f;
#pragma unroll
        for (int nt = 0; nt < 8; ++nt) {
            m = fmaxf(m, acc[mt][nt][rh * 2 + 0]);
            m = fmaxf(m, acc[mt][nt][rh * 2 + 1]);
        }
        m = fmaxf(m, __shfl_xor_sync(0xffffffffu, m, 1));
        m = fmaxf(m, __shfl_xor_sync(0xffffffffu, m, 2));
        float s = 0.f;
#pragma unroll
        for (int nt = 0; nt < 8; ++nt) {
#pragma unroll
            for (int c = 0; c < 2; ++c) {
                const float e = exp2f((acc[mt][nt][rh * 2 + c] - m) * LOG2E);
                acc[mt][nt][rh * 2 + c] = e;     // reuse regs as exp values
                s += e;
            }
        }
        s += __shfl_xor_sync(0xffffffffu, s, 1);
        s += __shfl_xor_sync(0xffffffffu, s, 2);
        mloc[rid] = m;
        if (tig == 0) {
            const int row = mt * 16 + rh * 8 + grp;
            redM[row * 8 + nw] = m;
            redS[row * 8 + nw] = s;
        }
    }
    __syncthreads();

#pragma unroll
    for (int rid = 0; rid < 4; ++rid) {
        const int mt = rid >> 1, rh = rid & 1;
        const int row = mt * 16 + rh * 8 + grp;
        float M = -1e30f;
        float mv[8];
#pragma unroll
        for (int j = 0; j < 8; ++j) {
            mv[j] = redM[row * 8 + j];
            M = fmaxf(M, mv[j]);
        }
        float S = 0.f;
#pragma unroll
        for (int j = 0; j < 8; ++j)
            S += redS[row * 8 + j] * exp2f((mv[j] - M) * LOG2E);
        const float scale = exp2f((mloc[rid] - M) * LOG2E) / S;

        float* orow = out + (size_t)(rowblk * MT + row) * KCLUST + nw * 64;
#pragma unroll
        for (int nt = 0; nt < 8; ++nt) {
            float2 v;
            v.x = acc[mt][nt][rh * 2 + 0] * scale;
            v.y = acc[mt][nt][rh * 2 + 1] * scale;
            *reinterpret_cast<float2*>(orow + nt * 8 + 2 * tig) = v;
        }
    }
}

// ---------------------------------------------------------------- launch
extern "C" void kernel_launch(void* const* d_in, const int* in_sizes, int n_in,
                              void* d_out, int out_size) {
    const float* x = (const float*)d_in[0];
    const float* cent = (const float*)d_in[1];
    if (n_in >= 2 && in_sizes[0] == KCLUST * DDIM && in_sizes[1] == NRTOT * DDIM) {
        const float* t = x; x = cent; cent = t;
    }
    float* out = (float*)d_out;

    prep_kernel<<<KCLUST, 128>>>(cent);
    kmeans_mma<<<NRTOT / MT, NTHR>>>(x, out);
}